// round 5
// baseline (speedup 1.0000x reference)
#include <cuda_runtime.h>
#include <cuda_bf16.h>
#include <float.h>

// Problem constants
#define BB 4
#define NN 1024
#define DD 1024
#define HH 16
#define DH 64
#define INNER 1024
#define BH 64          // B*H
#define MM 4096        // B*N
#define KDIM 1024
#define SCALE 0.125f

// Scratch (device globals; no allocation allowed)
__device__ float g_q[(size_t)BH * NN * DH];     // [bh, n, d]
__device__ float g_k[(size_t)BH * NN * DH];
__device__ float g_v[(size_t)BH * NN * DH];
__device__ float g_ao[(size_t)MM * INNER];      // [b, n, h, d] == [m, inner]

// ---------------------------------------------------------------------------
// bf16 split-3 tensor-core GEMM.
// C[M=4096, Nout] = A[M,1024] @ W[1024,Nout]  (+bias for mode 2)
// mode 0: scatter to g_q (head-major); mode 1: cols<1024 -> g_k, >=1024 -> g_v;
// mode 2: A is taken from g_ao (device-side! never pass __device__ symbol from
//         host), out = C + bias (row-major).
// A = Ahi + Alo (bf16 each), same for W; C = Ahi*Whi + Ahi*Wlo + Alo*Whi.
// CTA tile 128x128, BK=32, 8 warps (4m x 2n), warp tile 32x64, mma m16n8k16.
// ---------------------------------------------------------------------------
__device__ __forceinline__ void mma_bf16(float* c, const unsigned* a,
                                         unsigned b0, unsigned b1) {
    asm volatile(
        "mma.sync.aligned.m16n8k16.row.col.f32.bf16.bf16.f32 "
        "{%0,%1,%2,%3}, {%4,%5,%6,%7}, {%8,%9}, {%0,%1,%2,%3};\n"
        : "+f"(c[0]), "+f"(c[1]), "+f"(c[2]), "+f"(c[3])
        : "r"(a[0]), "r"(a[1]), "r"(a[2]), "r"(a[3]), "r"(b0), "r"(b1));
}

__device__ __forceinline__ void split_bf16(float v, __nv_bfloat16& hi,
                                           __nv_bfloat16& lo) {
    hi = __float2bfloat16_rn(v);
    lo = __float2bfloat16_rn(v - __bfloat162float(hi));
}

__device__ __forceinline__ void store_elem(int m, int c, float v, int mode,
                                           const float* __restrict__ bias,
                                           float* __restrict__ outp) {
    if (mode == 2) {
        outp[(size_t)m * 1024 + c] = v + bias[c];
        return;
    }
    int bb = m >> 10, n = m & 1023;
    float* dst;
    int ci = c;
    if (mode == 0) {
        dst = g_q;
    } else if (c < 1024) {
        dst = g_k;
    } else {
        dst = g_v;
        ci = c - 1024;
    }
    int h = ci >> 6, d = ci & 63;
    dst[(((size_t)(bb * 16 + h)) * 1024 + n) * 64 + d] = v;
}

__global__ __launch_bounds__(256) void mma_gemm(
    const float* __restrict__ Ain, const float* __restrict__ W,
    const float* __restrict__ bias, float* __restrict__ outp,
    int Nout, int mode)
{
    // Device-side A selection: g_ao must be resolved in device code.
    const float* __restrict__ A = (mode == 2) ? (const float*)g_ao : Ain;

    // [plane: 0=hi 1=lo][row][col], 40-elem padded rows
    __shared__ __nv_bfloat16 As[2][128][40];   // [.][m][k]
    __shared__ __nv_bfloat16 Bs[2][128][40];   // [.][n][k]

    const int tid  = threadIdx.x;
    const int warp = tid >> 5, lane = tid & 31;
    const int wm = (warp & 3) * 32;     // warp row base within CTA tile
    const int wn = (warp >> 2) * 64;    // warp col base
    const int g  = lane >> 2, t4 = lane & 3;
    const int bm = blockIdx.y * 128, bn = blockIdx.x * 128;

    float acc[2][8][4];
#pragma unroll
    for (int mi = 0; mi < 2; mi++)
#pragma unroll
        for (int ni = 0; ni < 8; ni++)
#pragma unroll
            for (int r = 0; r < 4; r++) acc[mi][ni][r] = 0.f;

    float4 pa[4], pb[4];

    // ---- tile loaders --------------------------------------------------
    auto load_tile = [&](int k0) {
#pragma unroll
        for (int i = 0; i < 4; i++) {
            int f = tid + 256 * i;
            int r  = f >> 3, c4 = (f & 7) * 4;            // A: 128 rows x 8 f4
            pa[i] = *(const float4*)(A + (size_t)(bm + r) * KDIM + k0 + c4);
            int kr = f >> 5, n4 = (f & 31) * 4;           // W: 32 rows x 32 f4
            pb[i] = *(const float4*)(W + (size_t)(k0 + kr) * Nout + bn + n4);
        }
    };
    auto convert_store = [&]() {
#pragma unroll
        for (int i = 0; i < 4; i++) {
            int f = tid + 256 * i;
            int r = f >> 3, c4 = (f & 7) * 4;
            const float* va = (const float*)&pa[i];
#pragma unroll
            for (int j = 0; j < 4; j++) {
                __nv_bfloat16 hi, lo;
                split_bf16(va[j], hi, lo);
                As[0][r][c4 + j] = hi;
                As[1][r][c4 + j] = lo;
            }
            int kr = f >> 5, n4 = (f & 31) * 4;
            const float* vb = (const float*)&pb[i];
#pragma unroll
            for (int j = 0; j < 4; j++) {
                __nv_bfloat16 hi, lo;
                split_bf16(vb[j], hi, lo);
                Bs[0][n4 + j][kr] = hi;      // transposed: [n][k]
                Bs[1][n4 + j][kr] = lo;
            }
        }
    };

    // ---- pipeline ------------------------------------------------------
    load_tile(0);
    convert_store();
    __syncthreads();

    for (int it = 0; it < KDIM / 32; it++) {
        const bool more = (it + 1 < KDIM / 32);
        if (more) load_tile((it + 1) * 32);

        // compute: 2 k16-steps
#pragma unroll
        for (int ks = 0; ks < 32; ks += 16) {
            unsigned ahi[2][4], alo[2][4];
#pragma unroll
            for (int mi = 0; mi < 2; mi++) {
                int rm = wm + mi * 16;
                int kc = ks + t4 * 2;
                ahi[mi][0] = *(const unsigned*)&As[0][rm + g][kc];
                ahi[mi][1] = *(const unsigned*)&As[0][rm + g + 8][kc];
                ahi[mi][2] = *(const unsigned*)&As[0][rm + g][kc + 8];
                ahi[mi][3] = *(const unsigned*)&As[0][rm + g + 8][kc + 8];
                alo[mi][0] = *(const unsigned*)&As[1][rm + g][kc];
                alo[mi][1] = *(const unsigned*)&As[1][rm + g + 8][kc];
                alo[mi][2] = *(const unsigned*)&As[1][rm + g][kc + 8];
                alo[mi][3] = *(const unsigned*)&As[1][rm + g + 8][kc + 8];
            }
#pragma unroll
            for (int ni = 0; ni < 8; ni++) {
                int nb = wn + ni * 8 + g;
                int kc = ks + t4 * 2;
                unsigned bh0 = *(const unsigned*)&Bs[0][nb][kc];
                unsigned bh1 = *(const unsigned*)&Bs[0][nb][kc + 8];
                unsigned bl0 = *(const unsigned*)&Bs[1][nb][kc];
                unsigned bl1 = *(const unsigned*)&Bs[1][nb][kc + 8];
#pragma unroll
                for (int mi = 0; mi < 2; mi++) {
                    mma_bf16(acc[mi][ni], ahi[mi], bh0, bh1);
                    mma_bf16(acc[mi][ni], ahi[mi], bl0, bl1);
                    mma_bf16(acc[mi][ni], alo[mi], bh0, bh1);
                }
            }
        }
        __syncthreads();
        if (more) {
            convert_store();
            __syncthreads();
        }
    }

    // ---- epilogue ------------------------------------------------------
#pragma unroll
    for (int mi = 0; mi < 2; mi++)
#pragma unroll
        for (int ni = 0; ni < 8; ni++) {
            int row = bm + wm + mi * 16 + g;
            int col = bn + wn + ni * 8 + t4 * 2;
            store_elem(row,     col,     acc[mi][ni][0], mode, bias, outp);
            store_elem(row,     col + 1, acc[mi][ni][1], mode, bias, outp);
            store_elem(row + 8, col,     acc[mi][ni][2], mode, bias, outp);
            store_elem(row + 8, col + 1, acc[mi][ni][3], mode, bias, outp);
        }
}

// ---------------------------------------------------------------------------
// Flash attention with rel_pos bias + row/col masks. (unchanged this round)
// CTA = (query tile of 64, bh). 256 threads as 16(ty: q-rows) x 16(tx).
// ---------------------------------------------------------------------------
__global__ __launch_bounds__(256) void attn_kernel(
    const float* __restrict__ rel, const int* __restrict__ qmask,
    const int* __restrict__ cmask)
{
    const int bh = blockIdx.y;          // 0..63
    const int q0 = blockIdx.x * 64;
    const int b = bh >> 4;

    __shared__ float Qs[64][65];
    __shared__ float Ks[32][65];
    __shared__ float Vs[32][65];
    __shared__ float Ss[64][33];
    __shared__ float qm[64];
    __shared__ float cm[32];

    const int tid = threadIdx.x;
    const int ty = tid >> 4, tx = tid & 15;

    const float* qbase = g_q + ((size_t)bh * NN + q0) * DH;
    for (int t = tid; t < 64 * 16; t += 256) {
        int r = t >> 4, c4 = (t & 15) * 4;
        float4 v = *(const float4*)(qbase + r * 64 + c4);
        Qs[r][c4 + 0] = v.x; Qs[r][c4 + 1] = v.y;
        Qs[r][c4 + 2] = v.z; Qs[r][c4 + 3] = v.w;
    }
    if (tid < 64) qm[tid] = (qmask[b * NN + q0 + tid] != 0) ? 1.f : 0.f;
    __syncthreads();

    float m_i[4], l_i[4], o[4][4];
#pragma unroll
    for (int i = 0; i < 4; i++) {
        m_i[i] = -FLT_MAX;
        l_i[i] = 0.f;
#pragma unroll
        for (int d = 0; d < 4; d++) o[i][d] = 0.f;
    }

    for (int j0 = 0; j0 < NN; j0 += 32) {
        const float* kbase = g_k + ((size_t)bh * NN + j0) * DH;
        const float* vbase = g_v + ((size_t)bh * NN + j0) * DH;
        for (int t = tid; t < 32 * 16; t += 256) {
            int r = t >> 4, c4 = (t & 15) * 4;
            float4 kv = *(const float4*)(kbase + r * 64 + c4);
            float4 vv = *(const float4*)(vbase + r * 64 + c4);
            Ks[r][c4 + 0] = kv.x; Ks[r][c4 + 1] = kv.y;
            Ks[r][c4 + 2] = kv.z; Ks[r][c4 + 3] = kv.w;
            Vs[r][c4 + 0] = vv.x; Vs[r][c4 + 1] = vv.y;
            Vs[r][c4 + 2] = vv.z; Vs[r][c4 + 3] = vv.w;
        }
        if (tid < 32) cm[tid] = (cmask[b * NN + j0 + tid] != 0) ? 1.f : 0.f;
        __syncthreads();

        float s[4][2];
#pragma unroll
        for (int ii = 0; ii < 4; ii++) { s[ii][0] = 0.f; s[ii][1] = 0.f; }
#pragma unroll 8
        for (int kk = 0; kk < 64; kk++) {
            float k0v = Ks[tx * 2 + 0][kk];
            float k1v = Ks[tx * 2 + 1][kk];
#pragma unroll
            for (int ii = 0; ii < 4; ii++) {
                float qv = Qs[ty * 4 + ii][kk];
                s[ii][0] += qv * k0v;
                s[ii][1] += qv * k1v;
            }
        }

        const float* relbase = rel + ((size_t)bh * NN + q0) * NN + j0;
        float c0 = cm[tx * 2 + 0];
        float c1 = cm[tx * 2 + 1];

#pragma unroll
        for (int ii = 0; ii < 4; ii++) {
            int qi = ty * 4 + ii;
            float2 r2 = *(const float2*)(relbase + (size_t)qi * NN + tx * 2);
            float s0 = s[ii][0] * SCALE + r2.x;
            float s1 = s[ii][1] * SCALE + r2.y;
            if (c0 == 0.f) s0 = -FLT_MAX;
            if (c1 == 0.f) s1 = -FLT_MAX;
            if (qm[qi] == 0.f) { s0 = -FLT_MAX; s1 = -FLT_MAX; }

            float mx = fmaxf(s0, s1);
            mx = fmaxf(mx, __shfl_xor_sync(0xffffffffu, mx, 1));
            mx = fmaxf(mx, __shfl_xor_sync(0xffffffffu, mx, 2));
            mx = fmaxf(mx, __shfl_xor_sync(0xffffffffu, mx, 4));
            mx = fmaxf(mx, __shfl_xor_sync(0xffffffffu, mx, 8));

            float m_new = fmaxf(m_i[ii], mx);
            float alpha = __expf(m_i[ii] - m_new);
            float p0 = __expf(s0 - m_new);
            float p1 = __expf(s1 - m_new);
            float rs = p0 + p1;
            rs += __shfl_xor_sync(0xffffffffu, rs, 1);
            rs += __shfl_xor_sync(0xffffffffu, rs, 2);
            rs += __shfl_xor_sync(0xffffffffu, rs, 4);
            rs += __shfl_xor_sync(0xffffffffu, rs, 8);

            l_i[ii] = l_i[ii] * alpha + rs;
            m_i[ii] = m_new;
#pragma unroll
            for (int d = 0; d < 4; d++) o[ii][d] *= alpha;
            Ss[qi][tx * 2 + 0] = p0;
            Ss[qi][tx * 2 + 1] = p1;
        }
        __syncthreads();

#pragma unroll 4
        for (int j = 0; j < 32; j++) {
            float vv[4];
#pragma unroll
            for (int d = 0; d < 4; d++) vv[d] = Vs[j][tx * 4 + d];
#pragma unroll
            for (int ii = 0; ii < 4; ii++) {
                float pij = Ss[ty * 4 + ii][j];
#pragma unroll
                for (int d = 0; d < 4; d++) o[ii][d] += pij * vv[d];
            }
        }
        __syncthreads();
    }

    const int h = bh & 15;
#pragma unroll
    for (int ii = 0; ii < 4; ii++) {
        int qi = q0 + ty * 4 + ii;
        float inv = 1.f / l_i[ii];
        float* dst = g_ao + (((size_t)b * NN + qi) * HH + h) * DH + tx * 4;
        float4 w;
        w.x = o[ii][0] * inv; w.y = o[ii][1] * inv;
        w.z = o[ii][2] * inv; w.w = o[ii][3] * inv;
        *(float4*)dst = w;
    }
}

// ---------------------------------------------------------------------------
// Launch. Inputs: x, rel_pos, query_mask, context_mask, Wq, Wkv, Wo, bo
// NOTE: never pass __device__ symbols (g_ao etc.) as kernel args from host —
// the host-side symbol address is garbage. mode==2 resolves g_ao in device code.
// ---------------------------------------------------------------------------
extern "C" void kernel_launch(void* const* d_in, const int* in_sizes, int n_in,
                              void* d_out, int out_size) {
    const float* x    = (const float*)d_in[0];
    const float* rel  = (const float*)d_in[1];
    const int*   qmsk = (const int*)d_in[2];
    const int*   cmsk = (const int*)d_in[3];
    const float* Wq   = (const float*)d_in[4];
    const float* Wkv  = (const float*)d_in[5];
    const float* Wo   = (const float*)d_in[6];
    const float* bo   = (const float*)d_in[7];
    float* out = (float*)d_out;

    // Q projection: 4096 x 1024
    mma_gemm<<<dim3(1024 / 128, 4096 / 128), 256>>>(x, Wq, nullptr, nullptr, 1024, 0);
    // KV projection: 4096 x 2048
    mma_gemm<<<dim3(2048 / 128, 4096 / 128), 256>>>(x, Wkv, nullptr, nullptr, 2048, 1);
    // Attention
    attn_kernel<<<dim3(NN / 64, BH), 256>>>(rel, qmsk, cmsk);
    // Output projection + bias: 4096 x 1024 (A = g_ao, resolved device-side)
    mma_gemm<<<dim3(1024 / 128, 4096 / 128), 256>>>(nullptr, Wo, bo, out, 1024, 2);
}

// round 6
// speedup vs baseline: 2.6707x; 2.6707x over previous
#include <cuda_runtime.h>
#include <cuda_bf16.h>
#include <float.h>

// Problem constants
#define BB 4
#define NN 1024
#define HH 16
#define DH 64
#define INNER 1024
#define BH 64          // B*H
#define MM 4096        // B*N
#define KDIM 1024
#define SCALE 0.125f

// ---------------------------------------------------------------------------
// Scratch (device globals). bf16 hi/lo planes everywhere.
// ---------------------------------------------------------------------------
__device__ __nv_bfloat16 g_xhi[(size_t)MM * KDIM],  g_xlo[(size_t)MM * KDIM];
__device__ __nv_bfloat16 g_wqhi[(size_t)KDIM * 1024],  g_wqlo[(size_t)KDIM * 1024];
__device__ __nv_bfloat16 g_wkvhi[(size_t)KDIM * 2048], g_wkvlo[(size_t)KDIM * 2048];
__device__ __nv_bfloat16 g_wohi[(size_t)KDIM * 1024],  g_wolo[(size_t)KDIM * 1024];
__device__ __nv_bfloat16 g_qhi[(size_t)BH * NN * DH], g_qlo[(size_t)BH * NN * DH];
__device__ __nv_bfloat16 g_khi[(size_t)BH * NN * DH], g_klo[(size_t)BH * NN * DH];
__device__ __nv_bfloat16 g_vhi[(size_t)BH * NN * DH], g_vlo[(size_t)BH * NN * DH];
__device__ __nv_bfloat16 g_aohi[(size_t)MM * INNER], g_aolo[(size_t)MM * INNER];

// ---------------------------------------------------------------------------
// Helpers
// ---------------------------------------------------------------------------
__device__ __forceinline__ void mma_bf16(float* c, const unsigned* a,
                                         unsigned b0, unsigned b1) {
    asm volatile(
        "mma.sync.aligned.m16n8k16.row.col.f32.bf16.bf16.f32 "
        "{%0,%1,%2,%3}, {%4,%5,%6,%7}, {%8,%9}, {%0,%1,%2,%3};\n"
        : "+f"(c[0]), "+f"(c[1]), "+f"(c[2]), "+f"(c[3])
        : "r"(a[0]), "r"(a[1]), "r"(a[2]), "r"(a[3]), "r"(b0), "r"(b1));
}

__device__ __forceinline__ unsigned su32(const void* p) {
    return (unsigned)__cvta_generic_to_shared(p);
}
__device__ __forceinline__ void ldsm4(unsigned& r0, unsigned& r1, unsigned& r2,
                                      unsigned& r3, unsigned a) {
    asm volatile("ldmatrix.sync.aligned.m8n8.x4.shared.b16 {%0,%1,%2,%3},[%4];"
                 : "=r"(r0), "=r"(r1), "=r"(r2), "=r"(r3) : "r"(a));
}
__device__ __forceinline__ void ldsm4t(unsigned& r0, unsigned& r1, unsigned& r2,
                                       unsigned& r3, unsigned a) {
    asm volatile("ldmatrix.sync.aligned.m8n8.x4.trans.shared.b16 {%0,%1,%2,%3},[%4];"
                 : "=r"(r0), "=r"(r1), "=r"(r2), "=r"(r3) : "r"(a));
}
#define CPA16(dst, src) \
    asm volatile("cp.async.cg.shared.global [%0],[%1],16;\n" ::"r"(dst), "l"(src))
#define CP_COMMIT asm volatile("cp.async.commit_group;\n")
#define CP_WAIT0 asm volatile("cp.async.wait_group 0;\n")
#define CP_WAIT1 asm volatile("cp.async.wait_group 1;\n")

__device__ __forceinline__ void split_bf16(float v, __nv_bfloat16& hi,
                                           __nv_bfloat16& lo) {
    hi = __float2bfloat16_rn(v);
    lo = __float2bfloat16_rn(v - __bfloat162float(hi));
}
__device__ __forceinline__ unsigned pack2(__nv_bfloat16 a, __nv_bfloat16 b) {
    __nv_bfloat162 h(a, b);
    return *(unsigned*)&h;
}

// ---------------------------------------------------------------------------
// Convert fp32 input -> bf16 hi/lo planes (scratch selected device-side).
// which: 0=x, 1=Wq, 2=Wkv, 3=Wo
// ---------------------------------------------------------------------------
__global__ __launch_bounds__(256) void convert_split_kernel(
    const float* __restrict__ in, int n4, int which)
{
    __nv_bfloat16 *hi, *lo;
    if (which == 0)      { hi = g_xhi;   lo = g_xlo; }
    else if (which == 1) { hi = g_wqhi;  lo = g_wqlo; }
    else if (which == 2) { hi = g_wkvhi; lo = g_wkvlo; }
    else                 { hi = g_wohi;  lo = g_wolo; }
    int i = blockIdx.x * blockDim.x + threadIdx.x;
    if (i >= n4) return;
    float4 v = ((const float4*)in)[i];
    __nv_bfloat16 h[4], l[4];
    split_bf16(v.x, h[0], l[0]); split_bf16(v.y, h[1], l[1]);
    split_bf16(v.z, h[2], l[2]); split_bf16(v.w, h[3], l[3]);
    ((ushort4*)hi)[i] = make_ushort4(*(unsigned short*)&h[0], *(unsigned short*)&h[1],
                                     *(unsigned short*)&h[2], *(unsigned short*)&h[3]);
    ((ushort4*)lo)[i] = make_ushort4(*(unsigned short*)&l[0], *(unsigned short*)&l[1],
                                     *(unsigned short*)&l[2], *(unsigned short*)&l[3]);
}

// ---------------------------------------------------------------------------
// bf16 split-3 GEMM, cp.async double-buffered + ldmatrix.
// C[M=4096, Nout] = A @ W. mode 0: ->Q planes; 1: ->K/V planes; 2: fp32 out+bias.
// A/W sources resolved device-side by mode. CTA 128x128, BK=16, 8 warps (4m,2n).
// ---------------------------------------------------------------------------
__device__ __forceinline__ void gemm_store(int m, int c, float v, int mode,
                                           const float* __restrict__ bias,
                                           float* __restrict__ outp) {
    if (mode == 2) { outp[(size_t)m * 1024 + c] = v + bias[c]; return; }
    int bb = m >> 10, n = m & 1023;
    __nv_bfloat16 *dhi, *dlo;
    int ci = c;
    if (mode == 0)        { dhi = g_qhi; dlo = g_qlo; }
    else if (c < 1024)    { dhi = g_khi; dlo = g_klo; }
    else                  { dhi = g_vhi; dlo = g_vlo; ci = c - 1024; }
    int h = ci >> 6, d = ci & 63;
    size_t idx = (((size_t)(bb * 16 + h)) * 1024 + n) * 64 + d;
    __nv_bfloat16 hi, lo;
    split_bf16(v, hi, lo);
    dhi[idx] = hi; dlo[idx] = lo;
}

__global__ __launch_bounds__(256, 2) void mma_gemm(
    const float* __restrict__ bias, float* __restrict__ outp,
    int Nout, int mode)
{
    const __nv_bfloat16 *ahi, *alo, *whi, *wlo;
    if (mode == 0)      { ahi = g_xhi;  alo = g_xlo;  whi = g_wqhi;  wlo = g_wqlo; }
    else if (mode == 1) { ahi = g_xhi;  alo = g_xlo;  whi = g_wkvhi; wlo = g_wkvlo; }
    else                { ahi = g_aohi; alo = g_aolo; whi = g_wohi;  wlo = g_wolo; }

    __shared__ __nv_bfloat16 As[2][2][128][24];   // [stage][plane][m][k(16)+8]
    __shared__ __nv_bfloat16 Bs[2][2][16][136];   // [stage][plane][k][n(128)+8]

    const int tid = threadIdx.x;
    const int warp = tid >> 5, lane = tid & 31;
    const int wm = (warp & 3) * 32, wn = (warp >> 2) * 64;
    const int g = lane >> 2, t4 = lane & 3;
    const int bm = blockIdx.y * 128, bn = blockIdx.x * 128;

    float acc[2][8][4];
#pragma unroll
    for (int mi = 0; mi < 2; mi++)
#pragma unroll
        for (int ni = 0; ni < 8; ni++)
#pragma unroll
            for (int r = 0; r < 4; r++) acc[mi][ni][r] = 0.f;

    // cp.async loaders: A plane chunk: 128 rows x 2 chunks; B: 16 rows x 16.
    const int ar = tid >> 1, ac = (tid & 1) * 8;
    const int br = tid >> 4, bc = (tid & 15) * 8;

    auto stage_load = [&](int st, int k0) {
        CPA16(su32(&As[st][0][ar][ac]), ahi + (size_t)(bm + ar) * KDIM + k0 + ac);
        CPA16(su32(&As[st][1][ar][ac]), alo + (size_t)(bm + ar) * KDIM + k0 + ac);
        CPA16(su32(&Bs[st][0][br][bc]), whi + (size_t)(k0 + br) * Nout + bn + bc);
        CPA16(su32(&Bs[st][1][br][bc]), wlo + (size_t)(k0 + br) * Nout + bn + bc);
        CP_COMMIT;
    };

    stage_load(0, 0);

    const int NIT = KDIM / 16;
    for (int it = 0; it < NIT; it++) {
        const int st = it & 1;
        if (it + 1 < NIT) { stage_load(st ^ 1, (it + 1) * 16); CP_WAIT1; }
        else              { CP_WAIT0; }
        __syncthreads();

        // A fragments (hi/lo, 2 mi)
        unsigned fa_hi[2][4], fa_lo[2][4];
#pragma unroll
        for (int mi = 0; mi < 2; mi++) {
            int row = wm + mi * 16 + (lane & 15);
            int col = (lane >> 4) * 8;
            ldsm4(fa_hi[mi][0], fa_hi[mi][1], fa_hi[mi][2], fa_hi[mi][3],
                  su32(&As[st][0][row][col]));
            ldsm4(fa_lo[mi][0], fa_lo[mi][1], fa_lo[mi][2], fa_lo[mi][3],
                  su32(&As[st][1][row][col]));
        }
        // B fragments per n16 block (trans ldmatrix from [k][n])
#pragma unroll
        for (int nq = 0; nq < 4; nq++) {
            int row = lane & 15;
            int col = wn + nq * 16 + (lane >> 4) * 8;
            unsigned bh0e, bh1e, bh0o, bh1o, bl0e, bl1e, bl0o, bl1o;
            ldsm4t(bh0e, bh1e, bh0o, bh1o, su32(&Bs[st][0][row][col]));
            ldsm4t(bl0e, bl1e, bl0o, bl1o, su32(&Bs[st][1][row][col]));
#pragma unroll
            for (int mi = 0; mi < 2; mi++) {
                mma_bf16(acc[mi][nq * 2],     fa_hi[mi], bh0e, bh1e);
                mma_bf16(acc[mi][nq * 2],     fa_hi[mi], bl0e, bl1e);
                mma_bf16(acc[mi][nq * 2],     fa_lo[mi], bh0e, bh1e);
                mma_bf16(acc[mi][nq * 2 + 1], fa_hi[mi], bh0o, bh1o);
                mma_bf16(acc[mi][nq * 2 + 1], fa_hi[mi], bl0o, bl1o);
                mma_bf16(acc[mi][nq * 2 + 1], fa_lo[mi], bh0o, bh1o);
            }
        }
        __syncthreads();
    }

    // epilogue (fragment mapping proven in R5)
#pragma unroll
    for (int mi = 0; mi < 2; mi++)
#pragma unroll
        for (int ni = 0; ni < 8; ni++) {
            int row = bm + wm + mi * 16 + g;
            int col = bn + wn + ni * 8 + t4 * 2;
            gemm_store(row,     col,     acc[mi][ni][0], mode, bias, outp);
            gemm_store(row,     col + 1, acc[mi][ni][1], mode, bias, outp);
            gemm_store(row + 8, col,     acc[mi][ni][2], mode, bias, outp);
            gemm_store(row + 8, col + 1, acc[mi][ni][3], mode, bias, outp);
        }
}

// ---------------------------------------------------------------------------
// Flash attention, bf16 split-3 MMA. CTA: 64 q-rows x bh, 4 warps (16 q each).
// kv tile 64. Q/K/V from bf16 hi/lo planes. rel_pos fused; -FLT_MAX masking.
// ---------------------------------------------------------------------------
__global__ __launch_bounds__(128) void attn_kernel(
    const float* __restrict__ rel, const int* __restrict__ qmask,
    const int* __restrict__ cmask)
{
    // [K/V region][plane][kv][d+8]; Q staged into region 0 at prologue.
    __shared__ __nv_bfloat16 KV[2][2][64][72];
    __shared__ float cm[64];

    const int bh = blockIdx.y;
    const int q0 = blockIdx.x * 64;
    const int b = bh >> 4, h = bh & 15;
    const int tid = threadIdx.x;
    const int wq = tid >> 5, lane = tid & 31;
    const int g = lane >> 2, t4 = lane & 3;

    // ---- Q prologue: cp.async into KV[0], extract fragments ----
    {
        const __nv_bfloat16* qh = g_qhi + ((size_t)bh * NN + q0) * DH;
        const __nv_bfloat16* ql = g_qlo + ((size_t)bh * NN + q0) * DH;
#pragma unroll
        for (int i = 0; i < 4; i++) {
            int c = tid + 128 * i;          // 512 chunks per plane
            int r = c >> 3, cc = (c & 7) * 8;
            CPA16(su32(&KV[0][0][r][cc]), qh + (size_t)r * DH + cc);
            CPA16(su32(&KV[0][1][r][cc]), ql + (size_t)r * DH + cc);
        }
        CP_COMMIT; CP_WAIT0;
    }
    __syncthreads();

    unsigned aq_hi[4][4], aq_lo[4][4];      // [kstep][reg]
#pragma unroll
    for (int ks = 0; ks < 4; ks++) {
        int row = wq * 16 + (lane & 15);
        int col = ks * 16 + (lane >> 4) * 8;
        ldsm4(aq_hi[ks][0], aq_hi[ks][1], aq_hi[ks][2], aq_hi[ks][3],
              su32(&KV[0][0][row][col]));
        ldsm4(aq_lo[ks][0], aq_lo[ks][1], aq_lo[ks][2], aq_lo[ks][3],
              su32(&KV[0][1][row][col]));
    }
    __syncthreads();

    // per-lane rows
    const int row0 = q0 + wq * 16 + g;       // and row0+8
    const float qm0 = (qmask[b * NN + row0] != 0) ? 1.f : 0.f;
    const float qm1 = (qmask[b * NN + row0 + 8] != 0) ? 1.f : 0.f;
    const float* relr0 = rel + ((size_t)bh * NN + row0) * NN;
    const float* relr1 = relr0 + (size_t)8 * NN;

    float m0 = -FLT_MAX, m1 = -FLT_MAX, l0 = 0.f, l1 = 0.f;
    float acc_o[8][4];
#pragma unroll
    for (int i = 0; i < 8; i++)
#pragma unroll
        for (int r = 0; r < 4; r++) acc_o[i][r] = 0.f;

    for (int j0 = 0; j0 < NN; j0 += 64) {
        // ---- load K/V tile (hi/lo) ----
        {
            const __nv_bfloat16* kh = g_khi + ((size_t)bh * NN + j0) * DH;
            const __nv_bfloat16* kl = g_klo + ((size_t)bh * NN + j0) * DH;
            const __nv_bfloat16* vh = g_vhi + ((size_t)bh * NN + j0) * DH;
            const __nv_bfloat16* vl = g_vlo + ((size_t)bh * NN + j0) * DH;
#pragma unroll
            for (int i = 0; i < 4; i++) {
                int c = tid + 128 * i;
                int r = c >> 3, cc = (c & 7) * 8;
                CPA16(su32(&KV[0][0][r][cc]), kh + (size_t)r * DH + cc);
                CPA16(su32(&KV[0][1][r][cc]), kl + (size_t)r * DH + cc);
                CPA16(su32(&KV[1][0][r][cc]), vh + (size_t)r * DH + cc);
                CPA16(su32(&KV[1][1][r][cc]), vl + (size_t)r * DH + cc);
            }
            if (tid < 64) cm[tid] = (cmask[b * NN + j0 + tid] != 0) ? 1.f : 0.f;
            CP_COMMIT; CP_WAIT0;
        }
        __syncthreads();

        // ---- S = Q K^T (split-3) ----
        float s[8][4];
#pragma unroll
        for (int ni = 0; ni < 8; ni++)
#pragma unroll
            for (int r = 0; r < 4; r++) s[ni][r] = 0.f;

#pragma unroll
        for (int ks = 0; ks < 4; ks++) {
#pragma unroll
            for (int nq = 0; nq < 4; nq++) {
                // non-trans ldmatrix; rows = kv(n), cols = d(k)
                int row = nq * 16 + ((lane & 16) >> 1) + (lane & 7);
                int col = ks * 16 + (lane & 8);
                unsigned kh0e, kh1e, kh0o, kh1o, kl0e, kl1e, kl0o, kl1o;
                ldsm4(kh0e, kh1e, kh0o, kh1o, su32(&KV[0][0][row][col]));
                ldsm4(kl0e, kl1e, kl0o, kl1o, su32(&KV[0][1][row][col]));
                mma_bf16(s[nq * 2],     aq_hi[ks], kh0e, kh1e);
                mma_bf16(s[nq * 2],     aq_hi[ks], kl0e, kl1e);
                mma_bf16(s[nq * 2],     aq_lo[ks], kh0e, kh1e);
                mma_bf16(s[nq * 2 + 1], aq_hi[ks], kh0o, kh1o);
                mma_bf16(s[nq * 2 + 1], aq_hi[ks], kl0o, kl1o);
                mma_bf16(s[nq * 2 + 1], aq_lo[ks], kh0o, kh1o);
            }
        }

        // ---- bias + mask ----
#pragma unroll
        for (int ni = 0; ni < 8; ni++) {
            int col = ni * 8 + t4 * 2;
            float2 ra = *(const float2*)(relr0 + j0 + col);
            float2 rb = *(const float2*)(relr1 + j0 + col);
            float c0 = cm[col], c1 = cm[col + 1];
            s[ni][0] = (c0 * qm0 != 0.f) ? s[ni][0] * SCALE + ra.x : -FLT_MAX;
            s[ni][1] = (c1 * qm0 != 0.f) ? s[ni][1] * SCALE + ra.y : -FLT_MAX;
            s[ni][2] = (c0 * qm1 != 0.f) ? s[ni][2] * SCALE + rb.x : -FLT_MAX;
            s[ni][3] = (c1 * qm1 != 0.f) ? s[ni][3] * SCALE + rb.y : -FLT_MAX;
        }

        // ---- online softmax ----
        float mx0 = -FLT_MAX, mx1 = -FLT_MAX;
#pragma unroll
        for (int ni = 0; ni < 8; ni++) {
            mx0 = fmaxf(mx0, fmaxf(s[ni][0], s[ni][1]));
            mx1 = fmaxf(mx1, fmaxf(s[ni][2], s[ni][3]));
        }
        mx0 = fmaxf(mx0, __shfl_xor_sync(0xffffffffu, mx0, 1));
        mx0 = fmaxf(mx0, __shfl_xor_sync(0xffffffffu, mx0, 2));
        mx1 = fmaxf(mx1, __shfl_xor_sync(0xffffffffu, mx1, 1));
        mx1 = fmaxf(mx1, __shfl_xor_sync(0xffffffffu, mx1, 2));

        float mn0 = fmaxf(m0, mx0), mn1 = fmaxf(m1, mx1);
        float al0 = __expf(m0 - mn0), al1 = __expf(m1 - mn1);
        float sum0 = 0.f, sum1 = 0.f;
#pragma unroll
        for (int ni = 0; ni < 8; ni++) {
            s[ni][0] = __expf(s[ni][0] - mn0);
            s[ni][1] = __expf(s[ni][1] - mn0);
            s[ni][2] = __expf(s[ni][2] - mn1);
            s[ni][3] = __expf(s[ni][3] - mn1);
            sum0 += s[ni][0] + s[ni][1];
            sum1 += s[ni][2] + s[ni][3];
        }
        sum0 += __shfl_xor_sync(0xffffffffu, sum0, 1);
        sum0 += __shfl_xor_sync(0xffffffffu, sum0, 2);
        sum1 += __shfl_xor_sync(0xffffffffu, sum1, 1);
        sum1 += __shfl_xor_sync(0xffffffffu, sum1, 2);
        l0 = l0 * al0 + sum0; m0 = mn0;
        l1 = l1 * al1 + sum1; m1 = mn1;
#pragma unroll
        for (int i = 0; i < 8; i++) {
            acc_o[i][0] *= al0; acc_o[i][1] *= al0;
            acc_o[i][2] *= al1; acc_o[i][3] *= al1;
        }

        // ---- P fragments (hi/lo, in-register repack) + PV ----
#pragma unroll
        for (int kc = 0; kc < 4; kc++) {
            __nv_bfloat16 h00, l00, h01, l01, h10, l10, h11, l11;
            __nv_bfloat16 h20, l20, h21, l21, h30, l30, h31, l31;
            split_bf16(s[kc * 2][0], h00, l00);  split_bf16(s[kc * 2][1], h01, l01);
            split_bf16(s[kc * 2][2], h10, l10);  split_bf16(s[kc * 2][3], h11, l11);
            split_bf16(s[kc * 2 + 1][0], h20, l20); split_bf16(s[kc * 2 + 1][1], h21, l21);
            split_bf16(s[kc * 2 + 1][2], h30, l30); split_bf16(s[kc * 2 + 1][3], h31, l31);
            unsigned ap_hi[4] = { pack2(h00, h01), pack2(h10, h11),
                                  pack2(h20, h21), pack2(h30, h31) };
            unsigned ap_lo[4] = { pack2(l00, l01), pack2(l10, l11),
                                  pack2(l20, l21), pack2(l30, l31) };
#pragma unroll
            for (int nd = 0; nd < 4; nd++) {
                // trans ldmatrix: rows = kv(k), cols = d(n)
                int row = kc * 16 + (lane & 15);
                int col = nd * 16 + (lane >> 4) * 8;
                unsigned vh0e, vh1e, vh0o, vh1o, vl0e, vl1e, vl0o, vl1o;
                ldsm4t(vh0e, vh1e, vh0o, vh1o, su32(&KV[1][0][row][col]));
                ldsm4t(vl0e, vl1e, vl0o, vl1o, su32(&KV[1][1][row][col]));
                mma_bf16(acc_o[nd * 2],     ap_hi, vh0e, vh1e);
                mma_bf16(acc_o[nd * 2],     ap_hi, vl0e, vl1e);
                mma_bf16(acc_o[nd * 2],     ap_lo, vh0e, vh1e);
                mma_bf16(acc_o[nd * 2 + 1], ap_hi, vh0o, vh1o);
                mma_bf16(acc_o[nd * 2 + 1], ap_hi, vl0o, vl1o);
                mma_bf16(acc_o[nd * 2 + 1], ap_lo, vh0o, vh1o);
            }
        }
        __syncthreads();
    }

    // ---- epilogue: o/l -> bf16 hi/lo planes of g_ao [b,n,h,d] ----
    float inv0 = 1.f / l0, inv1 = 1.f / l1;
    int r0g = q0 + wq * 16 + g;
#pragma unroll
    for (int nd = 0; nd < 8; nd++) {
        int d = nd * 8 + t4 * 2;
        size_t i0 = (((size_t)b * NN + r0g) * HH + h) * DH + d;
        size_t i1 = (((size_t)b * NN + r0g + 8) * HH + h) * DH + d;
        __nv_bfloat16 hi, lo;
        split_bf16(acc_o[nd][0] * inv0, hi, lo); g_aohi[i0] = hi;     g_aolo[i0] = lo;
        split_bf16(acc_o[nd][1] * inv0, hi, lo); g_aohi[i0 + 1] = hi; g_aolo[i0 + 1] = lo;
        split_bf16(acc_o[nd][2] * inv1, hi, lo); g_aohi[i1] = hi;     g_aolo[i1] = lo;
        split_bf16(acc_o[nd][3] * inv1, hi, lo); g_aohi[i1 + 1] = hi; g_aolo[i1 + 1] = lo;
    }
}

// ---------------------------------------------------------------------------
// Launch. Inputs: x, rel_pos, query_mask, context_mask, Wq, Wkv, Wo, bo
// (device scratch symbols only ever referenced from device code)
// ---------------------------------------------------------------------------
extern "C" void kernel_launch(void* const* d_in, const int* in_sizes, int n_in,
                              void* d_out, int out_size) {
    const float* x    = (const float*)d_in[0];
    const float* rel  = (const float*)d_in[1];
    const int*   qmsk = (const int*)d_in[2];
    const int*   cmsk = (const int*)d_in[3];
    const float* Wq   = (const float*)d_in[4];
    const float* Wkv  = (const float*)d_in[5];
    const float* Wo   = (const float*)d_in[6];
    const float* bo   = (const float*)d_in[7];
    float* out = (float*)d_out;

    // bf16 hi/lo pre-conversion
    convert_split_kernel<<<(MM * KDIM / 4 + 255) / 256, 256>>>(x,   MM * KDIM / 4,   0);
    convert_split_kernel<<<(KDIM * 1024 / 4 + 255) / 256, 256>>>(Wq,  KDIM * 1024 / 4, 1);
    convert_split_kernel<<<(KDIM * 2048 / 4 + 255) / 256, 256>>>(Wkv, KDIM * 2048 / 4, 2);
    convert_split_kernel<<<(KDIM * 1024 / 4 + 255) / 256, 256>>>(Wo,  KDIM * 1024 / 4, 3);

    // Projections
    mma_gemm<<<dim3(8, 32),  256>>>(nullptr, nullptr, 1024, 0);   // Q
    mma_gemm<<<dim3(16, 32), 256>>>(nullptr, nullptr, 2048, 1);   // K,V
    // Attention
    attn_kernel<<<dim3(NN / 64, BH), 128>>>(rel, qmsk, cmsk);
    // Output projection + bias
    mma_gemm<<<dim3(8, 32),  256>>>(bo, out, 1024, 2);
}

// round 9
// speedup vs baseline: 2.7845x; 1.0426x over previous
#include <cuda_runtime.h>
#include <cuda_bf16.h>
#include <float.h>
#include <stdint.h>

// Problem constants
#define BB 4
#define NN 1024
#define HH 16
#define DH 64
#define INNER 1024
#define BH 64          // B*H
#define MM 4096        // B*N
#define KDIM 1024
#define SCALE 0.125f

// ---------------------------------------------------------------------------
// Scratch (device globals). bf16 hi/lo planes (R6-proven layouts).
// x, ao: [m][k]. Weights: [k][n]. q/k/v: [bh][n][d].
// ---------------------------------------------------------------------------
__device__ __nv_bfloat16 g_xhi[(size_t)MM * KDIM],  g_xlo[(size_t)MM * KDIM];
__device__ __nv_bfloat16 g_wqhi[(size_t)KDIM * 1024],  g_wqlo[(size_t)KDIM * 1024];
__device__ __nv_bfloat16 g_wkvhi[(size_t)KDIM * 2048], g_wkvlo[(size_t)KDIM * 2048];
__device__ __nv_bfloat16 g_wohi[(size_t)KDIM * 1024],  g_wolo[(size_t)KDIM * 1024];
__device__ __nv_bfloat16 g_qhi[(size_t)BH * NN * DH], g_qlo[(size_t)BH * NN * DH];
__device__ __nv_bfloat16 g_khi[(size_t)BH * NN * DH], g_klo[(size_t)BH * NN * DH];
__device__ __nv_bfloat16 g_vhi[(size_t)BH * NN * DH], g_vlo[(size_t)BH * NN * DH];
__device__ __nv_bfloat16 g_aohi[(size_t)MM * INNER], g_aolo[(size_t)MM * INNER];

// ---------------------------------------------------------------------------
// Helpers (all proven R5/R6)
// ---------------------------------------------------------------------------
__device__ __forceinline__ void mma_bf16(float* c, const unsigned* a,
                                         unsigned b0, unsigned b1) {
    asm volatile(
        "mma.sync.aligned.m16n8k16.row.col.f32.bf16.bf16.f32 "
        "{%0,%1,%2,%3}, {%4,%5,%6,%7}, {%8,%9}, {%0,%1,%2,%3};\n"
        : "+f"(c[0]), "+f"(c[1]), "+f"(c[2]), "+f"(c[3])
        : "r"(a[0]), "r"(a[1]), "r"(a[2]), "r"(a[3]), "r"(b0), "r"(b1));
}
__device__ __forceinline__ unsigned su32(const void* p) {
    return (unsigned)__cvta_generic_to_shared(p);
}
__device__ __forceinline__ void ldsm4(unsigned& r0, unsigned& r1, unsigned& r2,
                                      unsigned& r3, unsigned a) {
    asm volatile("ldmatrix.sync.aligned.m8n8.x4.shared.b16 {%0,%1,%2,%3},[%4];"
                 : "=r"(r0), "=r"(r1), "=r"(r2), "=r"(r3) : "r"(a));
}
__device__ __forceinline__ void ldsm4t(unsigned& r0, unsigned& r1, unsigned& r2,
                                       unsigned& r3, unsigned a) {
    asm volatile("ldmatrix.sync.aligned.m8n8.x4.trans.shared.b16 {%0,%1,%2,%3},[%4];"
                 : "=r"(r0), "=r"(r1), "=r"(r2), "=r"(r3) : "r"(a));
}
#define CPA16(dst, src) \
    asm volatile("cp.async.cg.shared.global [%0],[%1],16;\n" ::"r"(dst), "l"(src))
#define CP_COMMIT asm volatile("cp.async.commit_group;\n")
#define CP_WAIT0 asm volatile("cp.async.wait_group 0;\n")
#define CP_WAIT1 asm volatile("cp.async.wait_group 1;\n")

__device__ __forceinline__ void split_bf16(float v, __nv_bfloat16& hi,
                                           __nv_bfloat16& lo) {
    hi = __float2bfloat16_rn(v);
    lo = __float2bfloat16_rn(v - __bfloat162float(hi));
}
__device__ __forceinline__ unsigned pack2(__nv_bfloat16 a, __nv_bfloat16 b) {
    __nv_bfloat162 h(a, b);
    return *(unsigned*)&h;
}

// ---------------------------------------------------------------------------
// Convert fp32 -> bf16 hi/lo planes. which: 0=x, 1=Wq, 2=Wkv, 3=Wo  (R6-proven)
// ---------------------------------------------------------------------------
__global__ __launch_bounds__(256) void convert_split_kernel(
    const float* __restrict__ in, int n4, int which)
{
    __nv_bfloat16 *hi, *lo;
    if (which == 0)      { hi = g_xhi;   lo = g_xlo; }
    else if (which == 1) { hi = g_wqhi;  lo = g_wqlo; }
    else if (which == 2) { hi = g_wkvhi; lo = g_wkvlo; }
    else                 { hi = g_wohi;  lo = g_wolo; }
    int i = blockIdx.x * blockDim.x + threadIdx.x;
    if (i >= n4) return;
    float4 v = ((const float4*)in)[i];
    __nv_bfloat16 h[4], l[4];
    split_bf16(v.x, h[0], l[0]); split_bf16(v.y, h[1], l[1]);
    split_bf16(v.z, h[2], l[2]); split_bf16(v.w, h[3], l[3]);
    ((ushort4*)hi)[i] = make_ushort4(*(unsigned short*)&h[0], *(unsigned short*)&h[1],
                                     *(unsigned short*)&h[2], *(unsigned short*)&h[3]);
    ((ushort4*)lo)[i] = make_ushort4(*(unsigned short*)&l[0], *(unsigned short*)&l[1],
                                     *(unsigned short*)&l[2], *(unsigned short*)&l[3]);
}

// ---------------------------------------------------------------------------
// bf16 split-3 GEMM, 3-stage cp.async + ldmatrix (compute body proven R6).
// mode 0: fused QKV — global cols [0,3072): <1024 Q, <2048 K, else V.
// mode 2: out = g_ao @ Wo + bias (fp32).
// CTA 128x128, BK=16, 8 warps (4m x 2n). Dynamic smem 62976B.
// ---------------------------------------------------------------------------
#define GEMM_SMEM ((3 * 2 * 128 * 24 + 3 * 2 * 16 * 136) * 2)

__device__ __forceinline__ void gemm_store(int m, int c, float v, int mode,
                                           const float* __restrict__ bias,
                                           float* __restrict__ outp) {
    if (mode == 2) { outp[(size_t)m * 1024 + c] = v + bias[c]; return; }
    int bb = m >> 10, n = m & 1023;
    __nv_bfloat16 *dhi, *dlo;
    int ci = c;
    if (c < 1024)         { dhi = g_qhi; dlo = g_qlo; }
    else if (c < 2048)    { dhi = g_khi; dlo = g_klo; ci = c - 1024; }
    else                  { dhi = g_vhi; dlo = g_vlo; ci = c - 2048; }
    int h = ci >> 6, d = ci & 63;
    size_t idx = (((size_t)(bb * 16 + h)) * 1024 + n) * 64 + d;
    __nv_bfloat16 hi, lo;
    split_bf16(v, hi, lo);
    dhi[idx] = hi; dlo[idx] = lo;
}

__global__ __launch_bounds__(256) void mma_gemm(
    const float* __restrict__ bias, float* __restrict__ outp, int mode)
{
    extern __shared__ __nv_bfloat16 smg[];
    __nv_bfloat16* Asb = smg;                       // [st][pl][128][24]
    __nv_bfloat16* Bsb = smg + 3 * 2 * 128 * 24;    // [st][pl][16][136]
#define ASADDR(st, pl, r, c) (Asb + ((((st) * 2 + (pl)) * 128 + (r)) * 24) + (c))
#define BSADDR(st, pl, r, c) (Bsb + ((((st) * 2 + (pl)) * 16 + (r)) * 136) + (c))

    const int tid = threadIdx.x;
    const int warp = tid >> 5, lane = tid & 31;
    const int wm = (warp & 3) * 32, wn = (warp >> 2) * 64;
    const int g = lane >> 2, t4 = lane & 3;
    const int bm = blockIdx.y * 128, bn = blockIdx.x * 128;

    // per-CTA uniform source selection
    const __nv_bfloat16 *ahi, *alo, *whi, *wlo;
    int strideW, bnl;
    if (mode == 2)        { ahi = g_aohi; alo = g_aolo; whi = g_wohi;  wlo = g_wolo;  strideW = 1024; bnl = bn; }
    else if (bn < 1024)   { ahi = g_xhi;  alo = g_xlo;  whi = g_wqhi;  wlo = g_wqlo;  strideW = 1024; bnl = bn; }
    else                  { ahi = g_xhi;  alo = g_xlo;  whi = g_wkvhi; wlo = g_wkvlo; strideW = 2048; bnl = bn - 1024; }

    float acc[2][8][4];
#pragma unroll
    for (int mi = 0; mi < 2; mi++)
#pragma unroll
        for (int ni = 0; ni < 8; ni++)
#pragma unroll
            for (int r = 0; r < 4; r++) acc[mi][ni][r] = 0.f;

    const int ar = tid >> 1, ac = (tid & 1) * 8;
    const int br = tid >> 4, bc = (tid & 15) * 8;

    auto stage_load = [&](int st, int k0) {
        CPA16(su32(ASADDR(st, 0, ar, ac)), ahi + (size_t)(bm + ar) * KDIM + k0 + ac);
        CPA16(su32(ASADDR(st, 1, ar, ac)), alo + (size_t)(bm + ar) * KDIM + k0 + ac);
        CPA16(su32(BSADDR(st, 0, br, bc)), whi + (size_t)(k0 + br) * strideW + bnl + bc);
        CPA16(su32(BSADDR(st, 1, br, bc)), wlo + (size_t)(k0 + br) * strideW + bnl + bc);
        CP_COMMIT;
    };

    stage_load(0, 0);
    stage_load(1, 16);

    const int NIT = KDIM / 16;      // 64
    int st = 0;
    for (int it = 0; it < NIT; it++) {
        CP_WAIT1;                   // stage `it` complete; `it+1` may be in flight
        __syncthreads();            // all threads done with stage (it-1)'s compute
        if (it + 2 < NIT) {
            int nst = st + 2; if (nst >= 3) nst -= 3;
            stage_load(nst, (it + 2) * 16);
        }

        // ---- compute stage st (R6-proven body) ----
        unsigned fa_hi[2][4], fa_lo[2][4];
#pragma unroll
        for (int mi = 0; mi < 2; mi++) {
            int row = wm + mi * 16 + (lane & 15);
            int col = (lane >> 4) * 8;
            ldsm4(fa_hi[mi][0], fa_hi[mi][1], fa_hi[mi][2], fa_hi[mi][3],
                  su32(ASADDR(st, 0, row, col)));
            ldsm4(fa_lo[mi][0], fa_lo[mi][1], fa_lo[mi][2], fa_lo[mi][3],
                  su32(ASADDR(st, 1, row, col)));
        }
#pragma unroll
        for (int nq = 0; nq < 4; nq++) {
            int row = lane & 15;
            int col = wn + nq * 16 + (lane >> 4) * 8;
            unsigned bh0e, bh1e, bh0o, bh1o, bl0e, bl1e, bl0o, bl1o;
            ldsm4t(bh0e, bh1e, bh0o, bh1o, su32(BSADDR(st, 0, row, col)));
            ldsm4t(bl0e, bl1e, bl0o, bl1o, su32(BSADDR(st, 1, row, col)));
#pragma unroll
            for (int mi = 0; mi < 2; mi++) {
                mma_bf16(acc[mi][nq * 2],     fa_hi[mi], bh0e, bh1e);
                mma_bf16(acc[mi][nq * 2],     fa_hi[mi], bl0e, bl1e);
                mma_bf16(acc[mi][nq * 2],     fa_lo[mi], bh0e, bh1e);
                mma_bf16(acc[mi][nq * 2 + 1], fa_hi[mi], bh0o, bh1o);
                mma_bf16(acc[mi][nq * 2 + 1], fa_hi[mi], bl0o, bl1o);
                mma_bf16(acc[mi][nq * 2 + 1], fa_lo[mi], bh0o, bh1o);
            }
        }
        if (++st >= 3) st = 0;
    }

    // epilogue (fragment mapping proven R5/R6)
#pragma unroll
    for (int mi = 0; mi < 2; mi++)
#pragma unroll
        for (int ni = 0; ni < 8; ni++) {
            int row = bm + wm + mi * 16 + g;
            int col = bn + wn + ni * 8 + t4 * 2;
            gemm_store(row,     col,     acc[mi][ni][0], mode, bias, outp);
            gemm_store(row,     col + 1, acc[mi][ni][1], mode, bias, outp);
            gemm_store(row + 8, col,     acc[mi][ni][2], mode, bias, outp);
            gemm_store(row + 8, col + 1, acc[mi][ni][3], mode, bias, outp);
        }
#undef ASADDR
#undef BSADDR
}

// ---------------------------------------------------------------------------
// Flash attention, bf16 split-3 mma.sync (compute body proven R6), now with
// double-buffered KV tiles. Q/K/V layout [bh][n][d]. Dynamic smem 74240B.
// ---------------------------------------------------------------------------
#define ATTN_SMEM (2 * 2 * 2 * 64 * 72 * 2 + 2 * 64 * 4)

__global__ __launch_bounds__(128) void attn_kernel(
    const float* __restrict__ rel, const int* __restrict__ qmask,
    const int* __restrict__ cmask)
{
    extern __shared__ char sma[];
    __nv_bfloat16* KVb = (__nv_bfloat16*)sma;   // [st][reg(K/V)][pl][64][72]
    float* cmb = (float*)(sma + 2 * 2 * 2 * 64 * 72 * 2);
#define KVADDR(st, rg, pl, r, c) \
    (KVb + (((((st) * 2 + (rg)) * 2 + (pl)) * 64 + (r)) * 72) + (c))

    const int bh = blockIdx.y;
    const int q0 = blockIdx.x * 64;
    const int b = bh >> 4, h = bh & 15;
    const int tid = threadIdx.x;
    const int wq = tid >> 5, lane = tid & 31;
    const int g = lane >> 2, t4 = lane & 3;

    // ---- Q prologue: into stage-0 K region ----
    {
        const __nv_bfloat16* qh = g_qhi + ((size_t)bh * NN + q0) * DH;
        const __nv_bfloat16* ql = g_qlo + ((size_t)bh * NN + q0) * DH;
#pragma unroll
        for (int i = 0; i < 4; i++) {
            int c = tid + 128 * i;
            int r = c >> 3, cc = (c & 7) * 8;
            CPA16(su32(KVADDR(0, 0, 0, r, cc)), qh + (size_t)r * DH + cc);
            CPA16(su32(KVADDR(0, 0, 1, r, cc)), ql + (size_t)r * DH + cc);
        }
        CP_COMMIT; CP_WAIT0;
    }
    __syncthreads();

    unsigned aq_hi[4][4], aq_lo[4][4];
#pragma unroll
    for (int ks = 0; ks < 4; ks++) {
        int row = wq * 16 + (lane & 15);
        int col = ks * 16 + (lane >> 4) * 8;
        ldsm4(aq_hi[ks][0], aq_hi[ks][1], aq_hi[ks][2], aq_hi[ks][3],
              su32(KVADDR(0, 0, 0, row, col)));
        ldsm4(aq_lo[ks][0], aq_lo[ks][1], aq_lo[ks][2], aq_lo[ks][3],
              su32(KVADDR(0, 0, 1, row, col)));
    }
    __syncthreads();

    // KV tile loader (stage st, kv offset j0)
    auto load_kv = [&](int st, int j0) {
        const __nv_bfloat16* kh = g_khi + ((size_t)bh * NN + j0) * DH;
        const __nv_bfloat16* kl = g_klo + ((size_t)bh * NN + j0) * DH;
        const __nv_bfloat16* vh = g_vhi + ((size_t)bh * NN + j0) * DH;
        const __nv_bfloat16* vl = g_vlo + ((size_t)bh * NN + j0) * DH;
#pragma unroll
        for (int i = 0; i < 4; i++) {
            int c = tid + 128 * i;
            int r = c >> 3, cc = (c & 7) * 8;
            CPA16(su32(KVADDR(st, 0, 0, r, cc)), kh + (size_t)r * DH + cc);
            CPA16(su32(KVADDR(st, 0, 1, r, cc)), kl + (size_t)r * DH + cc);
            CPA16(su32(KVADDR(st, 1, 0, r, cc)), vh + (size_t)r * DH + cc);
            CPA16(su32(KVADDR(st, 1, 1, r, cc)), vl + (size_t)r * DH + cc);
        }
        if (tid < 64) cmb[st * 64 + tid] = (cmask[b * NN + j0 + tid] != 0) ? 1.f : 0.f;
        CP_COMMIT;
    };

    load_kv(0, 0);   // tile 0

    const int row0 = q0 + wq * 16 + g;
    const float qm0 = (qmask[b * NN + row0] != 0) ? 1.f : 0.f;
    const float qm1 = (qmask[b * NN + row0 + 8] != 0) ? 1.f : 0.f;
    const float* relr0 = rel + ((size_t)bh * NN + row0) * NN;
    const float* relr1 = relr0 + (size_t)8 * NN;

    float m0 = -FLT_MAX, m1 = -FLT_MAX, l0 = 0.f, l1 = 0.f;
    float acc_o[8][4];
#pragma unroll
    for (int i = 0; i < 8; i++)
#pragma unroll
        for (int r = 0; r < 4; r++) acc_o[i][r] = 0.f;

    for (int it = 0; it < NN / 64; it++) {
        const int st = it & 1;
        const int j0 = it * 64;

        CP_WAIT0;          // current tile resident
        __syncthreads();   // everyone done reading the buffer we're about to refill
        if (it + 1 < NN / 64) load_kv(st ^ 1, j0 + 64);   // overlapped with compute

        // ---- S = Q K^T (split-3; proven) ----
        float s[8][4];
#pragma unroll
        for (int ni = 0; ni < 8; ni++)
#pragma unroll
            for (int r = 0; r < 4; r++) s[ni][r] = 0.f;

#pragma unroll
        for (int ks = 0; ks < 4; ks++) {
#pragma unroll
            for (int nq = 0; nq < 4; nq++) {
                int row = nq * 16 + ((lane & 16) >> 1) + (lane & 7);
                int col = ks * 16 + (lane & 8);
                unsigned kh0e, kh1e, kh0o, kh1o, kl0e, kl1e, kl0o, kl1o;
                ldsm4(kh0e, kh1e, kh0o, kh1o, su32(KVADDR(st, 0, 0, row, col)));
                ldsm4(kl0e, kl1e, kl0o, kl1o, su32(KVADDR(st, 0, 1, row, col)));
                mma_bf16(s[nq * 2],     aq_hi[ks], kh0e, kh1e);
                mma_bf16(s[nq * 2],     aq_hi[ks], kl0e, kl1e);
                mma_bf16(s[nq * 2],     aq_lo[ks], kh0e, kh1e);
                mma_bf16(s[nq * 2 + 1], aq_hi[ks], kh0o, kh1o);
                mma_bf16(s[nq * 2 + 1], aq_hi[ks], kl0o, kl1o);
                mma_bf16(s[nq * 2 + 1], aq_lo[ks], kh0o, kh1o);
            }
        }

        // ---- bias + mask ----
#pragma unroll
        for (int ni = 0; ni < 8; ni++) {
            int col = ni * 8 + t4 * 2;
            float2 ra = *(const float2*)(relr0 + j0 + col);
            float2 rb = *(const float2*)(relr1 + j0 + col);
            float c0 = cmb[st * 64 + col], c1 = cmb[st * 64 + col + 1];
            s[ni][0] = (c0 * qm0 != 0.f) ? s[ni][0] * SCALE + ra.x : -FLT_MAX;
            s[ni][1] = (c1 * qm0 != 0.f) ? s[ni][1] * SCALE + ra.y : -FLT_MAX;
            s[ni][2] = (c0 * qm1 != 0.f) ? s[ni][2] * SCALE + rb.x : -FLT_MAX;
            s[ni][3] = (c1 * qm1 != 0.f) ? s[ni][3] * SCALE + rb.y : -FLT_MAX;
        }

        // ---- online softmax (proven) ----
        float mx0 = -FLT_MAX, mx1 = -FLT_MAX;
#pragma unroll
        for (int ni = 0; ni < 8; ni++) {
            mx0 = fmaxf(mx0, fmaxf(s[ni][0], s[ni][1]));
            mx1 = fmaxf(mx1, fmaxf(s[ni][2], s[ni][3]));
        }
        mx0 = fmaxf(mx0, __shfl_xor_sync(0xffffffffu, mx0, 1));
        mx0 = fmaxf(mx0, __shfl_xor_sync(0xffffffffu, mx0, 2));
        mx1 = fmaxf(mx1, __shfl_xor_sync(0xffffffffu, mx1, 1));
        mx1 = fmaxf(mx1, __shfl_xor_sync(0xffffffffu, mx1, 2));

        float mn0 = fmaxf(m0, mx0), mn1 = fmaxf(m1, mx1);
        float al0 = __expf(m0 - mn0), al1 = __expf(m1 - mn1);
        float sum0 = 0.f, sum1 = 0.f;
#pragma unroll
        for (int ni = 0; ni < 8; ni++) {
            s[ni][0] = __expf(s[ni][0] - mn0);
            s[ni][1] = __expf(s[ni][1] - mn0);
            s[ni][2] = __expf(s[ni][2] - mn1);
            s[ni][3] = __expf(s[ni][3] - mn1);
            sum0 += s[ni][0] + s[ni][1];
            sum1 += s[ni][2] + s[ni][3];
        }
        sum0 += __shfl_xor_sync(0xffffffffu, sum0, 1);
        sum0 += __shfl_xor_sync(0xffffffffu, sum0, 2);
        sum1 += __shfl_xor_sync(0xffffffffu, sum1, 1);
        sum1 += __shfl_xor_sync(0xffffffffu, sum1, 2);
        l0 = l0 * al0 + sum0; m0 = mn0;
        l1 = l1 * al1 + sum1; m1 = mn1;
#pragma unroll
        for (int i = 0; i < 8; i++) {
            acc_o[i][0] *= al0; acc_o[i][1] *= al0;
            acc_o[i][2] *= al1; acc_o[i][3] *= al1;
        }

        // ---- P repack + PV (proven) ----
#pragma unroll
        for (int kc = 0; kc < 4; kc++) {
            __nv_bfloat16 h00, l00, h01, l01, h10, l10, h11, l11;
            __nv_bfloat16 h20, l20, h21, l21, h30, l30, h31, l31;
            split_bf16(s[kc * 2][0], h00, l00);  split_bf16(s[kc * 2][1], h01, l01);
            split_bf16(s[kc * 2][2], h10, l10);  split_bf16(s[kc * 2][3], h11, l11);
            split_bf16(s[kc * 2 + 1][0], h20, l20); split_bf16(s[kc * 2 + 1][1], h21, l21);
            split_bf16(s[kc * 2 + 1][2], h30, l30); split_bf16(s[kc * 2 + 1][3], h31, l31);
            unsigned ap_hi[4] = { pack2(h00, h01), pack2(h10, h11),
                                  pack2(h20, h21), pack2(h30, h31) };
            unsigned ap_lo[4] = { pack2(l00, l01), pack2(l10, l11),
                                  pack2(l20, l21), pack2(l30, l31) };
#pragma unroll
            for (int nd = 0; nd < 4; nd++) {
                int row = kc * 16 + (lane & 15);
                int col = nd * 16 + (lane >> 4) * 8;
                unsigned vh0e, vh1e, vh0o, vh1o, vl0e, vl1e, vl0o, vl1o;
                ldsm4t(vh0e, vh1e, vh0o, vh1o, su32(KVADDR(st, 1, 0, row, col)));
                ldsm4t(vl0e, vl1e, vl0o, vl1o, su32(KVADDR(st, 1, 1, row, col)));
                mma_bf16(acc_o[nd * 2],     ap_hi, vh0e, vh1e);
                mma_bf16(acc_o[nd * 2],     ap_hi, vl0e, vl1e);
                mma_bf16(acc_o[nd * 2],     ap_lo, vh0e, vh1e);
                mma_bf16(acc_o[nd * 2 + 1], ap_hi, vh0o, vh1o);
                mma_bf16(acc_o[nd * 2 + 1], ap_hi, vl0o, vl1o);
                mma_bf16(acc_o[nd * 2 + 1], ap_lo, vh0o, vh1o);
            }
        }
    }

    // ---- epilogue -> g_ao planes [m][inner] ----
    float inv0 = 1.f / l0, inv1 = 1.f / l1;
    int r0g = q0 + wq * 16 + g;
#pragma unroll
    for (int nd = 0; nd < 8; nd++) {
        int d = nd * 8 + t4 * 2;
        size_t i0 = (((size_t)b * NN + r0g) * HH + h) * DH + d;
        size_t i1 = (((size_t)b * NN + r0g + 8) * HH + h) * DH + d;
        __nv_bfloat16 hi, lo;
        split_bf16(acc_o[nd][0] * inv0, hi, lo); g_aohi[i0] = hi;     g_aolo[i0] = lo;
        split_bf16(acc_o[nd][1] * inv0, hi, lo); g_aohi[i0 + 1] = hi; g_aolo[i0 + 1] = lo;
        split_bf16(acc_o[nd][2] * inv1, hi, lo); g_aohi[i1] = hi;     g_aolo[i1] = lo;
        split_bf16(acc_o[nd][3] * inv1, hi, lo); g_aohi[i1 + 1] = hi; g_aolo[i1 + 1] = lo;
    }
#undef KVADDR
}

// ---------------------------------------------------------------------------
// Launch. Inputs: x, rel_pos, query_mask, context_mask, Wq, Wkv, Wo, bo
// ---------------------------------------------------------------------------
extern "C" void kernel_launch(void* const* d_in, const int* in_sizes, int n_in,
                              void* d_out, int out_size) {
    const float* x    = (const float*)d_in[0];
    const float* rel  = (const float*)d_in[1];
    const int*   qmsk = (const int*)d_in[2];
    const int*   cmsk = (const int*)d_in[3];
    const float* Wq   = (const float*)d_in[4];
    const float* Wkv  = (const float*)d_in[5];
    const float* Wo   = (const float*)d_in[6];
    const float* bo   = (const float*)d_in[7];
    float* out = (float*)d_out;

    cudaFuncSetAttribute(mma_gemm, cudaFuncAttributeMaxDynamicSharedMemorySize,
                         GEMM_SMEM);
    cudaFuncSetAttribute(attn_kernel, cudaFuncAttributeMaxDynamicSharedMemorySize,
                         ATTN_SMEM);

    // conversions
    convert_split_kernel<<<(MM * KDIM / 4 + 255) / 256, 256>>>(x,   MM * KDIM / 4,   0);
    convert_split_kernel<<<(KDIM * 1024 / 4 + 255) / 256, 256>>>(Wq,  KDIM * 1024 / 4, 1);
    convert_split_kernel<<<(KDIM * 2048 / 4 + 255) / 256, 256>>>(Wkv, KDIM * 2048 / 4, 2);
    convert_split_kernel<<<(KDIM * 1024 / 4 + 255) / 256, 256>>>(Wo,  KDIM * 1024 / 4, 3);

    // fused Q+K+V projection: 3072 cols x 4096 rows
    mma_gemm<<<dim3(24, 32), 256, GEMM_SMEM>>>(nullptr, nullptr, 0);
    // attention (double-buffered)
    attn_kernel<<<dim3(NN / 64, BH), 128, ATTN_SMEM>>>(rel, qmsk, cmsk);
    // output projection + bias
    mma_gemm<<<dim3(8, 32), 256, GEMM_SMEM>>>(bo, out, 2);
}